// round 4
// baseline (speedup 1.0000x reference)
#include <cuda_runtime.h>

#define NN 50000
#define NE 800000
#define NG 128
#define FX 92
#define FE 41
#define H  64
#define NCONV 3
#define BN_EPS 1e-5f

__device__ float d_h[NN * H];
__device__ float d_agg[NN * H];
__device__ float d_P[NN * 4 * H];
__device__ float d_eap[NE * FE];
__device__ int   d_perm[NE];
__device__ int   g_srcS[NE];
__device__ int   g_dstS[NE];
__device__ int   d_deg[NN];
__device__ int   d_inc[NN];
__device__ int   d_cursor[NN];
__device__ int   d_bsum[128];
__device__ int   d_bpre[128];
__device__ float d_Wcat[NCONV * H * 4 * H];
__device__ float d_Ccomb[NCONV * FE * 2 * H];
__device__ float d_cbias[NCONV * 2 * H];
__device__ float d_colsum[H], d_colsq[H], d_scale[H], d_shift[H];
__device__ float d_gsum[NG * H];
__device__ int   d_gcnt[NG];

__device__ __forceinline__ float sigmoidf_(float x) { return 1.0f / (1.0f + __expf(-x)); }
__device__ __forceinline__ float softplusf_(float x) {
    return fmaxf(x, 0.0f) + __logf(1.0f + __expf(-fabsf(x)));
}

__global__ void k_zero() {
    int stride = gridDim.x * blockDim.x;
    for (int i = blockIdx.x * blockDim.x + threadIdx.x; i < NN * H; i += stride) {
        d_agg[i] = 0.0f;
        if (i < NN) d_deg[i] = 0;
        if (i < NG * H) d_gsum[i] = 0.0f;
        if (i < NG) d_gcnt[i] = 0;
    }
}

__global__ void k_prep(const float* __restrict__ W_emb2, const float* __restrict__ b_emb2,
                       const float* __restrict__ Wf, const float* __restrict__ bf,
                       const float* __restrict__ Ws, const float* __restrict__ bs) {
    const int SZ1 = NCONV * H * 4 * H;
    const int SZ2 = NCONV * FE * 2 * H;
    const int SZ3 = NCONV * 2 * H;
    int total = SZ1 + SZ2 + SZ3;
    int stride = gridDim.x * blockDim.x;
    for (int i = blockIdx.x * blockDim.x + threadIdx.x; i < total; i += stride) {
        if (i < SZ1) {
            int a = i / (H * 4 * H);
            int rem = i - a * (H * 4 * H);
            int r = rem / (4 * H);
            int c = rem - r * (4 * H);
            const float* M = ((c >> 6) & 1) ? Ws : Wf;
            int cc = c & 63;
            int rr = (c < 128) ? r : (r + H);
            d_Wcat[i] = M[a * 192 * H + rr * H + cc];
        } else if (i < SZ1 + SZ2) {
            int j = i - SZ1;
            int a = j / (FE * 2 * H);
            int rem = j - a * (FE * 2 * H);
            int k = rem / (2 * H);
            int c = rem - k * (2 * H);
            const float* M = (c < H) ? Wf : Ws;
            int cc = (c < H) ? c : (c - H);
            int base = a * 192 * H + 128 * H;
            float s = 0.0f;
            for (int m = 0; m < H; m++) s += W_emb2[k * H + m] * M[base + m * H + cc];
            d_Ccomb[j] = s;
        } else {
            int j = i - SZ1 - SZ2;
            int a = j / (2 * H);
            int c = j - a * (2 * H);
            const float* M = (c < H) ? Wf : Ws;
            const float* bb = (c < H) ? bf : bs;
            int cc = (c < H) ? c : (c - H);
            int base = a * 192 * H + 128 * H;
            float s = bb[a * H + cc];
            for (int m = 0; m < H; m++) s += b_emb2[m] * M[base + m * H + cc];
            d_cbias[j] = s;
        }
    }
}

__global__ void k_hist(const int* __restrict__ dst) {
    int stride = gridDim.x * blockDim.x;
    for (int e = blockIdx.x * blockDim.x + threadIdx.x; e < NE; e += stride)
        atomicAdd(&d_deg[dst[e]], 1);
}

__global__ void k_scan1() {
    __shared__ int s[512];
    int t = threadIdx.x;
    int i = blockIdx.x * 512 + t;
    int v = (i < NN) ? d_deg[i] : 0;
    s[t] = v;
    __syncthreads();
    for (int d = 1; d < 512; d <<= 1) {
        int tv = (t >= d) ? s[t - d] : 0;
        __syncthreads();
        s[t] += tv;
        __syncthreads();
    }
    if (i < NN) d_inc[i] = s[t];
    if (t == 511) d_bsum[blockIdx.x] = s[511];
}

__global__ void k_scan2(int nb) {
    __shared__ int s[128];
    int t = threadIdx.x;
    int v = (t < nb) ? d_bsum[t] : 0;
    s[t] = v;
    __syncthreads();
    for (int d = 1; d < 128; d <<= 1) {
        int tv = (t >= d) ? s[t - d] : 0;
        __syncthreads();
        s[t] += tv;
        __syncthreads();
    }
    if (t < nb) d_bpre[t] = s[t] - v;
}

__global__ void k_scan3() {
    int i = blockIdx.x * blockDim.x + threadIdx.x;
    if (i < NN) d_cursor[i] = d_inc[i] - d_deg[i] + d_bpre[i >> 9];
}

__global__ void k_scatter(const int* __restrict__ dst) {
    int stride = gridDim.x * blockDim.x;
    for (int e = blockIdx.x * blockDim.x + threadIdx.x; e < NE; e += stride) {
        int p = atomicAdd(&d_cursor[dst[e]], 1);
        d_perm[p] = e;
    }
}

__global__ void k_permute(const float* __restrict__ ea,
                          const int* __restrict__ src, const int* __restrict__ dst) {
    int gid = blockIdx.x * blockDim.x + threadIdx.x;
    int j = gid >> 6;
    int l = gid & 63;
    if (j >= NE) return;
    int e = d_perm[j];
    if (l < FE)           d_eap[j * FE + l] = ea[e * FE + l];
    else if (l == FE)     g_dstS[j] = dst[e];
    else if (l == FE + 1) g_srcS[j] = src[e];
}

__global__ void __launch_bounds__(256) k_emb(const float* __restrict__ x,
                                             const float* __restrict__ W,
                                             const float* __restrict__ b) {
    __shared__ float Xs[64 * 93];
    int tid = threadIdx.x;
    int base = blockIdx.x * 64;
    for (int t = tid; t < 64 * FX; t += 256) {
        int r = t / FX, k = t - r * FX;
        int row = base + r;
        Xs[r * 93 + k] = (row < NN) ? x[row * FX + k] : 0.0f;
    }
    __syncthreads();
    int i0 = tid & 31, g = tid >> 5;
    float acc0[8], acc1[8];
#pragma unroll
    for (int m = 0; m < 8; m++) { float bv = b[g * 8 + m]; acc0[m] = bv; acc1[m] = bv; }
    for (int k = 0; k < FX; k++) {
        float a0 = Xs[i0 * 93 + k];
        float a1 = Xs[(i0 + 32) * 93 + k];
        const float4* w = (const float4*)(W + k * H + g * 8);
        float4 w0 = w[0], w1 = w[1];
        acc0[0] += a0 * w0.x; acc0[1] += a0 * w0.y; acc0[2] += a0 * w0.z; acc0[3] += a0 * w0.w;
        acc0[4] += a0 * w1.x; acc0[5] += a0 * w1.y; acc0[6] += a0 * w1.z; acc0[7] += a0 * w1.w;
        acc1[0] += a1 * w0.x; acc1[1] += a1 * w0.y; acc1[2] += a1 * w0.z; acc1[3] += a1 * w0.w;
        acc1[4] += a1 * w1.x; acc1[5] += a1 * w1.y; acc1[6] += a1 * w1.z; acc1[7] += a1 * w1.w;
    }
    int r0 = base + i0, r1 = base + i0 + 32;
    if (r0 < NN) {
        float4* o = (float4*)(d_h + r0 * H + g * 8);
        o[0] = make_float4(acc0[0], acc0[1], acc0[2], acc0[3]);
        o[1] = make_float4(acc0[4], acc0[5], acc0[6], acc0[7]);
    }
    if (r1 < NN) {
        float4* o = (float4*)(d_h + r1 * H + g * 8);
        o[0] = make_float4(acc1[0], acc1[1], acc1[2], acc1[3]);
        o[1] = make_float4(acc1[4], acc1[5], acc1[6], acc1[7]);
    }
}

__global__ void __launch_bounds__(512) k_P(int a) {
    extern __shared__ float sm[];
    float* Hs = sm;
    float* Ws = sm + 64 * 65;
    int tid = threadIdx.x;
    if (blockIdx.x == 0 && tid < 64) { d_colsum[tid] = 0.0f; d_colsq[tid] = 0.0f; }
    int base = blockIdx.x * 64;
    for (int t = tid; t < 64 * 64; t += 512) {
        int r = t >> 6, k = t & 63;
        int row = base + r;
        Hs[r * 65 + k] = (row < NN) ? d_h[row * H + k] : 0.0f;
    }
    for (int t = tid; t < 64 * 256; t += 512) Ws[t] = d_Wcat[a * 16384 + t];
    __syncthreads();
    int i = tid & 63, g = tid >> 6;
    float acc[32];
#pragma unroll
    for (int m = 0; m < 32; m++) acc[m] = 0.0f;
    for (int k = 0; k < 64; k++) {
        float av = Hs[i * 65 + k];
        const float4* w = (const float4*)(Ws + k * 256 + g * 32);
#pragma unroll
        for (int q = 0; q < 8; q++) {
            float4 wv = w[q];
            acc[q * 4 + 0] += av * wv.x;
            acc[q * 4 + 1] += av * wv.y;
            acc[q * 4 + 2] += av * wv.z;
            acc[q * 4 + 3] += av * wv.w;
        }
    }
    int row = base + i;
    if (row < NN) {
        float4* o = (float4*)(d_P + row * 256 + g * 32);
#pragma unroll
        for (int q = 0; q < 8; q++)
            o[q] = make_float4(acc[q * 4], acc[q * 4 + 1], acc[q * 4 + 2], acc[q * 4 + 3]);
    }
}

__global__ void __launch_bounds__(256) k_edge(int a) {
    extern __shared__ float sm[];
    float* As   = sm;
    float* Wcs  = As + 64 * 45;
    float* bias = Wcs + FE * 128;
    float* EF   = bias + 128;
    float* MS   = EF + 64 * 129;
    int*   dsts = (int*)(MS + 64 * 64);
    int*   srcs = dsts + 64;

    int tid = threadIdx.x;
    int base = blockIdx.x * 64;

    for (int t = tid; t < 64 * FE; t += 256) {
        int r = t / FE, k = t - r * FE;
        As[r * 45 + k] = d_eap[base * FE + t];
    }
    for (int t = tid; t < FE * 128; t += 256) Wcs[t] = d_Ccomb[a * FE * 128 + t];
    if (tid < 128) bias[tid] = d_cbias[a * 128 + tid];
    if (tid < 64) dsts[tid] = g_dstS[base + tid];
    else if (tid < 128) srcs[tid - 64] = g_srcS[base + tid - 64];
    __syncthreads();

    int i0 = tid & 31, g = tid >> 5;
    float acc0[16], acc1[16];
#pragma unroll
    for (int m = 0; m < 16; m++) { acc0[m] = 0.0f; acc1[m] = 0.0f; }
    for (int k = 0; k < FE; k++) {
        float a0 = As[i0 * 45 + k];
        float a1 = As[(i0 + 32) * 45 + k];
        const float4* w = (const float4*)(Wcs + k * 128 + g * 16);
#pragma unroll
        for (int q = 0; q < 4; q++) {
            float4 wv = w[q];
            acc0[q * 4 + 0] += a0 * wv.x; acc0[q * 4 + 1] += a0 * wv.y;
            acc0[q * 4 + 2] += a0 * wv.z; acc0[q * 4 + 3] += a0 * wv.w;
            acc1[q * 4 + 0] += a1 * wv.x; acc1[q * 4 + 1] += a1 * wv.y;
            acc1[q * 4 + 2] += a1 * wv.z; acc1[q * 4 + 3] += a1 * wv.w;
        }
    }
#pragma unroll
    for (int m = 0; m < 16; m++) {
        EF[i0 * 129 + g * 16 + m] = acc0[m];
        EF[(i0 + 32) * 129 + g * 16 + m] = acc1[m];
    }
    __syncthreads();

    int c = tid & 63;
    int esub = tid >> 6;
    for (int it = 0; it < 16; it++) {
        int ei = it * 4 + esub;
        int dn = dsts[ei], sn = srcs[ei];
        float af = EF[ei * 129 + c] + bias[c]
                 + d_P[dn * 256 + c] + d_P[sn * 256 + 128 + c];
        float as_ = EF[ei * 129 + 64 + c] + bias[64 + c]
                  + d_P[dn * 256 + 64 + c] + d_P[sn * 256 + 192 + c];
        MS[ei * 64 + c] = sigmoidf_(af) * softplusf_(as_);
    }
    __syncthreads();

    if (tid < 64) {
        float run = 0.0f;
        int prev = dsts[0];
        for (int e = 0; e < 64; e++) {
            int dn = dsts[e];
            if (dn != prev) {
                atomicAdd(&d_agg[prev * 64 + tid], run);
                run = 0.0f;
                prev = dn;
            }
            run += MS[e * 64 + tid];
        }
        atomicAdd(&d_agg[prev * 64 + tid], run);
    }
}

__global__ void k_bnstat() {
    int tid = threadIdx.x;
    int stride = gridDim.x * blockDim.x;
    float s = 0.0f, sq = 0.0f;
    for (int idx = blockIdx.x * blockDim.x + tid; idx < NN * H; idx += stride) {
        float v = d_h[idx] + d_agg[idx];
        d_h[idx] = v;
        d_agg[idx] = 0.0f;
        s += v;
        sq += v * v;
    }
    __shared__ float ss[256], qq[256];
    ss[tid] = s; qq[tid] = sq;
    __syncthreads();
    if (tid < 64) {
        float S = ss[tid] + ss[tid + 64] + ss[tid + 128] + ss[tid + 192];
        float Q = qq[tid] + qq[tid + 64] + qq[tid + 128] + qq[tid + 192];
        atomicAdd(&d_colsum[tid], S);
        atomicAdd(&d_colsq[tid], Q);
    }
}

__global__ void k_bnfin(const float* __restrict__ gamma, const float* __restrict__ beta) {
    int c = threadIdx.x;
    float mu = d_colsum[c] / (float)NN;
    float var = d_colsq[c] / (float)NN - mu * mu;
    var = fmaxf(var, 0.0f);
    float sc = gamma[c] * rsqrtf(var + BN_EPS);
    d_scale[c] = sc;
    d_shift[c] = beta[c] - mu * sc;
}

__global__ void k_bnapply(int pool, const int* __restrict__ batch) {
    int stride = gridDim.x * blockDim.x;
    for (int idx = blockIdx.x * blockDim.x + threadIdx.x; idx < NN * H; idx += stride) {
        int c = idx & 63;
        float v = d_scale[c] * d_h[idx] + d_shift[c];
        if (pool) {
            int r = idx >> 6;
            int gi = batch[r];
            atomicAdd(&d_gsum[gi * H + c], v);
            if (c == 0) atomicAdd(&d_gcnt[gi], 1);
        } else {
            d_h[idx] = fmaxf(v, 0.0f);
        }
    }
}

__global__ void k_mlp(const float* __restrict__ W1, const float* __restrict__ b1,
                      const float* __restrict__ W2, const float* __restrict__ b2,
                      const float* __restrict__ Wo, const float* __restrict__ bo,
                      float* __restrict__ out) {
    __shared__ float gv[64], y[64], red[64];
    int gi = blockIdx.x, c = threadIdx.x;
    float cnt = fmaxf((float)d_gcnt[gi], 1.0f);
    gv[c] = d_gsum[gi * H + c] / cnt;
    __syncthreads();
    float acc = b1[c];
    for (int k = 0; k < 64; k++) acc += gv[k] * W1[k * 64 + c];
    y[c] = softplusf_(acc);
    __syncthreads();
    acc = b2[c];
    for (int k = 0; k < 64; k++) acc += y[k] * W2[k * 64 + c];
    float y2 = softplusf_(acc);
    red[c] = y2 * Wo[c];
    __syncthreads();
    for (int s = 32; s > 0; s >>= 1) {
        if (c < s) red[c] += red[c + s];
        __syncthreads();
    }
    if (c == 0) out[gi] = red[0] + bo[0];
}

extern "C" void kernel_launch(void* const* d_in, const int* in_sizes, int n_in,
                              void* d_out, int out_size) {
    const float* x      = (const float*)d_in[0];
    const float* ea     = (const float*)d_in[1];
    const int*   eidx   = (const int*)d_in[2];
    const int*   batch  = (const int*)d_in[3];
    const float* W_emb1 = (const float*)d_in[4];
    const float* b_emb1 = (const float*)d_in[5];
    const float* W_emb2 = (const float*)d_in[6];
    const float* b_emb2 = (const float*)d_in[7];
    const float* Wf     = (const float*)d_in[8];
    const float* bf     = (const float*)d_in[9];
    const float* Ws     = (const float*)d_in[10];
    const float* bs     = (const float*)d_in[11];
    const float* gamma  = (const float*)d_in[12];
    const float* beta   = (const float*)d_in[13];
    const float* W1     = (const float*)d_in[14];
    const float* b1     = (const float*)d_in[15];
    const float* W2     = (const float*)d_in[16];
    const float* b2     = (const float*)d_in[17];
    const float* Wo     = (const float*)d_in[18];
    const float* bo     = (const float*)d_in[19];
    float* out = (float*)d_out;

    const int EDGE_SMEM = (64 * 45 + FE * 128 + 128 + 64 * 129 + 64 * 64) * 4 + 128 * 4;
    const int P_SMEM = (64 * 65 + 64 * 256) * 4;
    cudaFuncSetAttribute(k_edge, cudaFuncAttributeMaxDynamicSharedMemorySize, EDGE_SMEM);
    cudaFuncSetAttribute(k_P, cudaFuncAttributeMaxDynamicSharedMemorySize, P_SMEM);

    const int* src = eidx;
    const int* dst = eidx + NE;

    k_zero<<<2048, 256>>>();
    k_prep<<<256, 256>>>(W_emb2, b_emb2, Wf, bf, Ws, bs);
    k_hist<<<1024, 256>>>(dst);
    k_scan1<<<98, 512>>>();
    k_scan2<<<1, 128>>>(98);
    k_scan3<<<(NN + 255) / 256, 256>>>();
    k_scatter<<<1024, 256>>>(dst);
    k_permute<<<(NE * 64) / 256, 256>>>(ea, src, dst);
    k_emb<<<(NN + 63) / 64, 256>>>(x, W_emb1, b_emb1);

    for (int a = 0; a < NCONV; a++) {
        k_P<<<(NN + 63) / 64, 512, P_SMEM>>>(a);
        k_edge<<<NE / 64, 256, EDGE_SMEM>>>(a);
        k_bnstat<<<1024, 256>>>();
        k_bnfin<<<1, 64>>>(gamma + a * H, beta + a * H);
        k_bnapply<<<1024, 256>>>(a == NCONV - 1 ? 1 : 0, batch);
    }
    k_mlp<<<NG, 64>>>(W1, b1, W2, b2, Wo, bo, out);
}

// round 6
// speedup vs baseline: 1.3807x; 1.3807x over previous
#include <cuda_runtime.h>

#define NN 50000
#define NE 800000
#define NG 128
#define FX 92
#define FE 41
#define H  64
#define NCONV 3
#define BN_EPS 1e-5f
#define EFS 130

__device__ float d_h[NN * H];
__device__ float d_agg[NN * H];
__device__ float d_P[NN * 4 * H];
__device__ int   d_perm[NE];
__device__ int   g_srcS[NE];
__device__ int   g_dstS[NE];
__device__ int   d_deg[NN];
__device__ int   d_inc[NN];
__device__ int   d_cursor[NN];
__device__ int   d_bsum[128];
__device__ int   d_bpre[128];
__device__ float d_Wcat[NCONV * H * 4 * H];
__device__ float d_Ccomb[NCONV * FE * 2 * H];
__device__ float d_cbias[NCONV * 2 * H];
__device__ float d_colsum[H], d_colsq[H], d_scale[H], d_shift[H];
__device__ float d_gsum[NG * H];
__device__ int   d_gcnt[NG];

__device__ __forceinline__ float sigmoidf_(float x) { return 1.0f / (1.0f + __expf(-x)); }
__device__ __forceinline__ float softplusf_(float x) {
    return fmaxf(x, 0.0f) + __logf(1.0f + __expf(-fabsf(x)));
}
__device__ __forceinline__ unsigned long long packf2(float v) {
    unsigned long long r;
    unsigned int b = __float_as_uint(v);
    asm("mov.b64 %0, {%1, %1};" : "=l"(r) : "r"(b));
    return r;
}
__device__ __forceinline__ void fma2(unsigned long long& acc, unsigned long long a,
                                     unsigned long long b) {
    asm("fma.rn.f32x2 %0, %1, %2, %0;" : "+l"(acc) : "l"(a), "l"(b));
}

// ---- init: zero state + fold weights ----
__global__ void k_init(const float* __restrict__ W_emb2, const float* __restrict__ b_emb2,
                       const float* __restrict__ Wf, const float* __restrict__ bf,
                       const float* __restrict__ Ws, const float* __restrict__ bs) {
    int stride = gridDim.x * blockDim.x;
    int tid0 = blockIdx.x * blockDim.x + threadIdx.x;
    for (int i = tid0; i < NN * H; i += stride) {
        d_agg[i] = 0.0f;
        if (i < NN) d_deg[i] = 0;
        if (i < NG * H) d_gsum[i] = 0.0f;
        if (i < NG) d_gcnt[i] = 0;
    }
    const int SZ1 = NCONV * H * 4 * H;
    const int SZ2 = NCONV * FE * 2 * H;
    const int SZ3 = NCONV * 2 * H;
    int total = SZ1 + SZ2 + SZ3;
    for (int i = tid0; i < total; i += stride) {
        if (i < SZ1) {
            int a = i / (H * 4 * H);
            int rem = i - a * (H * 4 * H);
            int r = rem / (4 * H);
            int c = rem - r * (4 * H);
            const float* M = ((c >> 6) & 1) ? Ws : Wf;
            int cc = c & 63;
            int rr = (c < 128) ? r : (r + H);
            d_Wcat[i] = M[a * 192 * H + rr * H + cc];
        } else if (i < SZ1 + SZ2) {
            int j = i - SZ1;
            int a = j / (FE * 2 * H);
            int rem = j - a * (FE * 2 * H);
            int k = rem / (2 * H);
            int c = rem - k * (2 * H);
            const float* M = (c < H) ? Wf : Ws;
            int cc = (c < H) ? c : (c - H);
            int base = a * 192 * H + 128 * H;
            float s = 0.0f;
            for (int m = 0; m < H; m++) s += W_emb2[k * H + m] * M[base + m * H + cc];
            d_Ccomb[j] = s;
        } else {
            int j = i - SZ1 - SZ2;
            int a = j / (2 * H);
            int c = j - a * (2 * H);
            const float* M = (c < H) ? Wf : Ws;
            const float* bb = (c < H) ? bf : bs;
            int cc = (c < H) ? c : (c - H);
            int base = a * 192 * H + 128 * H;
            float s = bb[a * H + cc];
            for (int m = 0; m < H; m++) s += b_emb2[m] * M[base + m * H + cc];
            d_cbias[j] = s;
        }
    }
}

// ---- counting sort by dst ----
__global__ void k_hist(const int* __restrict__ dst) {
    int stride = gridDim.x * blockDim.x;
    for (int e = blockIdx.x * blockDim.x + threadIdx.x; e < NE; e += stride)
        atomicAdd(&d_deg[dst[e]], 1);
}

__global__ void k_scan1() {
    __shared__ int s[512];
    int t = threadIdx.x;
    int i = blockIdx.x * 512 + t;
    int v = (i < NN) ? d_deg[i] : 0;
    s[t] = v;
    __syncthreads();
    for (int d = 1; d < 512; d <<= 1) {
        int tv = (t >= d) ? s[t - d] : 0;
        __syncthreads();
        s[t] += tv;
        __syncthreads();
    }
    if (i < NN) d_inc[i] = s[t];
    if (t == 511) d_bsum[blockIdx.x] = s[511];
}

__global__ void k_scan2(int nb) {
    __shared__ int s[128];
    int t = threadIdx.x;
    int v = (t < nb) ? d_bsum[t] : 0;
    s[t] = v;
    __syncthreads();
    for (int d = 1; d < 128; d <<= 1) {
        int tv = (t >= d) ? s[t - d] : 0;
        __syncthreads();
        s[t] += tv;
        __syncthreads();
    }
    if (t < nb) d_bpre[t] = s[t] - v;
}

__global__ void k_scan3() {
    int i = blockIdx.x * blockDim.x + threadIdx.x;
    if (i < NN) d_cursor[i] = d_inc[i] - d_deg[i] + d_bpre[i >> 9];
}

__global__ void k_scatter(const int* __restrict__ dst) {
    int stride = gridDim.x * blockDim.x;
    for (int e = blockIdx.x * blockDim.x + threadIdx.x; e < NE; e += stride) {
        int p = atomicAdd(&d_cursor[dst[e]], 1);
        d_perm[p] = e;
    }
}

__global__ void k_permidx(const int* __restrict__ src, const int* __restrict__ dst) {
    int j = blockIdx.x * blockDim.x + threadIdx.x;
    if (j >= NE) return;
    int e = d_perm[j];
    g_dstS[j] = dst[e];
    g_srcS[j] = src[e];
}

// ---- node embedding ----
__global__ void __launch_bounds__(256) k_emb(const float* __restrict__ x,
                                             const float* __restrict__ W,
                                             const float* __restrict__ b) {
    __shared__ float Xs[64 * 93];
    int tid = threadIdx.x;
    int base = blockIdx.x * 64;
    for (int t = tid; t < 64 * FX; t += 256) {
        int r = t / FX, k = t - r * FX;
        int row = base + r;
        Xs[r * 93 + k] = (row < NN) ? x[row * FX + k] : 0.0f;
    }
    __syncthreads();
    int i0 = tid & 31, g = tid >> 5;
    float acc0[8], acc1[8];
#pragma unroll
    for (int m = 0; m < 8; m++) { float bv = b[g * 8 + m]; acc0[m] = bv; acc1[m] = bv; }
    for (int k = 0; k < FX; k++) {
        float a0 = Xs[i0 * 93 + k];
        float a1 = Xs[(i0 + 32) * 93 + k];
        const float4* w = (const float4*)(W + k * H + g * 8);
        float4 w0 = w[0], w1 = w[1];
        acc0[0] += a0 * w0.x; acc0[1] += a0 * w0.y; acc0[2] += a0 * w0.z; acc0[3] += a0 * w0.w;
        acc0[4] += a0 * w1.x; acc0[5] += a0 * w1.y; acc0[6] += a0 * w1.z; acc0[7] += a0 * w1.w;
        acc1[0] += a1 * w0.x; acc1[1] += a1 * w0.y; acc1[2] += a1 * w0.z; acc1[3] += a1 * w0.w;
        acc1[4] += a1 * w1.x; acc1[5] += a1 * w1.y; acc1[6] += a1 * w1.z; acc1[7] += a1 * w1.w;
    }
    int r0 = base + i0, r1 = base + i0 + 32;
    if (r0 < NN) {
        float4* o = (float4*)(d_h + r0 * H + g * 8);
        o[0] = make_float4(acc0[0], acc0[1], acc0[2], acc0[3]);
        o[1] = make_float4(acc0[4], acc0[5], acc0[6], acc0[7]);
    }
    if (r1 < NN) {
        float4* o = (float4*)(d_h + r1 * H + g * 8);
        o[0] = make_float4(acc1[0], acc1[1], acc1[2], acc1[3]);
        o[1] = make_float4(acc1[4], acc1[5], acc1[6], acc1[7]);
    }
}

// ---- node precompute (+ fused BN apply of previous layer) ----
__global__ void __launch_bounds__(512) k_P(int a, int applyBN) {
    extern __shared__ float sm[];
    float* Hs = sm;            // 64*65
    float* Ws = sm + 64 * 65;  // 64*256
    int tid = threadIdx.x;
    if (blockIdx.x == 0 && tid < 64) { d_colsum[tid] = 0.0f; d_colsq[tid] = 0.0f; }
    int base = blockIdx.x * 64;
    for (int t = tid; t < 64 * 64; t += 512) {
        int r = t >> 6, k = t & 63;
        int row = base + r;
        float v = 0.0f;
        if (row < NN) {
            v = d_h[row * H + k];
            if (applyBN) {
                v = fmaxf(fmaf(d_scale[k], v, d_shift[k]), 0.0f);
                d_h[row * H + k] = v;
            }
        }
        Hs[r * 65 + k] = v;
    }
    for (int t = tid; t < 64 * 256; t += 512) Ws[t] = d_Wcat[a * 16384 + t];
    __syncthreads();
    int i = tid & 63, g = tid >> 6;
    unsigned long long acc[16];
#pragma unroll
    for (int m = 0; m < 16; m++) acc[m] = 0ull;
    for (int k = 0; k < 64; k++) {
        unsigned long long av = packf2(Hs[i * 65 + k]);
        const ulonglong2* w = (const ulonglong2*)(Ws + k * 256 + g * 32);
#pragma unroll
        for (int q = 0; q < 8; q++) {
            ulonglong2 wv = w[q];
            fma2(acc[q * 2 + 0], av, wv.x);
            fma2(acc[q * 2 + 1], av, wv.y);
        }
    }
    int row = base + i;
    if (row < NN) {
        unsigned long long* o = (unsigned long long*)(d_P + row * 256 + g * 32);
#pragma unroll
        for (int m = 0; m < 16; m++) o[m] = acc[m];
    }
}

// ---- edge kernel: gather ea + GEMM (f32x2) + gate + sorted segment-sum ----
__global__ void __launch_bounds__(256) k_edge(int a, const float* __restrict__ ea) {
    extern __shared__ float sm[];
    float* As   = sm;                 // 64*45
    float* Wcs  = As + 64 * 45;       // 41*128
    float* bias = Wcs + FE * 128;     // 128
    float* EF   = bias + 128;         // 64*EFS
    int*   dsts = (int*)(EF + 64 * EFS);
    int*   srcs = dsts + 64;

    int tid = threadIdx.x;
    int base = blockIdx.x * 64;

    if (tid < 64) dsts[tid] = g_dstS[base + tid];
    else if (tid < 128) srcs[tid - 64] = g_srcS[base + tid - 64];
    for (int t = tid; t < 64 * FE; t += 256) {
        int r = t / FE, k = t - r * FE;
        As[r * 45 + k] = __ldg(&ea[d_perm[base + r] * FE + k]);
    }
    for (int t = tid; t < FE * 128; t += 256) Wcs[t] = d_Ccomb[a * FE * 128 + t];
    if (tid < 128) bias[tid] = d_cbias[a * 128 + tid];
    __syncthreads();

    int i0 = tid & 31, g = tid >> 5;
    unsigned long long acc0[8], acc1[8];
#pragma unroll
    for (int m = 0; m < 8; m++) { acc0[m] = 0ull; acc1[m] = 0ull; }
    for (int k = 0; k < FE; k++) {
        unsigned long long a0 = packf2(As[i0 * 45 + k]);
        unsigned long long a1 = packf2(As[(i0 + 32) * 45 + k]);
        const ulonglong2* w = (const ulonglong2*)(Wcs + k * 128 + g * 16);
#pragma unroll
        for (int q = 0; q < 4; q++) {
            ulonglong2 wv = w[q];
            fma2(acc0[q * 2 + 0], a0, wv.x);
            fma2(acc0[q * 2 + 1], a0, wv.y);
            fma2(acc1[q * 2 + 0], a1, wv.x);
            fma2(acc1[q * 2 + 1], a1, wv.y);
        }
    }
#pragma unroll
    for (int m = 0; m < 8; m++) {
        *(unsigned long long*)(&EF[i0 * EFS + g * 16 + 2 * m]) = acc0[m];
        *(unsigned long long*)(&EF[(i0 + 32) * EFS + g * 16 + 2 * m]) = acc1[m];
    }
    __syncthreads();

    int c = tid & 63;
    int esub = tid >> 6;
#pragma unroll 4
    for (int it = 0; it < 16; it++) {
        int ei = it * 4 + esub;
        int dn = dsts[ei], sn = srcs[ei];
        float af = EF[ei * EFS + c] + bias[c]
                 + __ldg(&d_P[dn * 256 + c]) + __ldg(&d_P[sn * 256 + 128 + c]);
        float as_ = EF[ei * EFS + 64 + c] + bias[64 + c]
                  + __ldg(&d_P[dn * 256 + 64 + c]) + __ldg(&d_P[sn * 256 + 192 + c]);
        EF[ei * EFS + c] = sigmoidf_(af) * softplusf_(as_);
    }
    __syncthreads();

    {
        int q = tid >> 6;
        int e0 = q * 16;
        float run = 0.0f;
        int prev = dsts[e0];
        for (int e = e0; e < e0 + 16; e++) {
            int dn = dsts[e];
            if (dn != prev) {
                atomicAdd(&d_agg[prev * 64 + c], run);
                run = 0.0f;
                prev = dn;
            }
            run += EF[e * EFS + c];
        }
        atomicAdd(&d_agg[prev * 64 + c], run);
    }
}

// ---- BN stats (h += agg) ----
__global__ void k_bnstat() {
    int tid = threadIdx.x;
    int stride = gridDim.x * blockDim.x;
    float s = 0.0f, sq = 0.0f;
    for (int idx = blockIdx.x * blockDim.x + tid; idx < NN * H; idx += stride) {
        float v = d_h[idx] + d_agg[idx];
        d_h[idx] = v;
        d_agg[idx] = 0.0f;
        s += v;
        sq += v * v;
    }
    __shared__ float ss[256], qq[256];
    ss[tid] = s; qq[tid] = sq;
    __syncthreads();
    if (tid < 64) {
        float S = ss[tid] + ss[tid + 64] + ss[tid + 128] + ss[tid + 192];
        float Q = qq[tid] + qq[tid + 64] + qq[tid + 128] + qq[tid + 192];
        atomicAdd(&d_colsum[tid], S);
        atomicAdd(&d_colsq[tid], Q);
    }
}

__global__ void k_bnfin(const float* __restrict__ gamma, const float* __restrict__ beta) {
    int c = threadIdx.x;
    float mu = d_colsum[c] / (float)NN;
    float var = d_colsq[c] / (float)NN - mu * mu;
    var = fmaxf(var, 0.0f);
    float sc = gamma[c] * rsqrtf(var + BN_EPS);
    d_scale[c] = sc;
    d_shift[c] = beta[c] - mu * sc;
}

// ---- last-layer BN apply + mean-pool accumulate ----
__global__ void k_pool(const int* __restrict__ batch) {
    int stride = gridDim.x * blockDim.x;
    for (int idx = blockIdx.x * blockDim.x + threadIdx.x; idx < NN * H; idx += stride) {
        int c = idx & 63;
        float v = fmaf(d_scale[c], d_h[idx], d_shift[c]);
        int r = idx >> 6;
        int gi = batch[r];
        atomicAdd(&d_gsum[gi * H + c], v);
        if (c == 0) atomicAdd(&d_gcnt[gi], 1);
    }
}

// ---- MLP head ----
__global__ void k_mlp(const float* __restrict__ W1, const float* __restrict__ b1,
                      const float* __restrict__ W2, const float* __restrict__ b2,
                      const float* __restrict__ Wo, const float* __restrict__ bo,
                      float* __restrict__ out) {
    __shared__ float gv[64], y[64], red[64];
    int gi = blockIdx.x, c = threadIdx.x;
    float cnt = fmaxf((float)d_gcnt[gi], 1.0f);
    gv[c] = d_gsum[gi * H + c] / cnt;
    __syncthreads();
    float acc = b1[c];
    for (int k = 0; k < 64; k++) acc += gv[k] * W1[k * 64 + c];
    y[c] = softplusf_(acc);
    __syncthreads();
    acc = b2[c];
    for (int k = 0; k < 64; k++) acc += y[k] * W2[k * 64 + c];
    float y2 = softplusf_(acc);
    red[c] = y2 * Wo[c];
    __syncthreads();
    for (int s = 32; s > 0; s >>= 1) {
        if (c < s) red[c] += red[c + s];
        __syncthreads();
    }
    if (c == 0) out[gi] = red[0] + bo[0];
}

extern "C" void kernel_launch(void* const* d_in, const int* in_sizes, int n_in,
                              void* d_out, int out_size) {
    const float* x      = (const float*)d_in[0];
    const float* ea     = (const float*)d_in[1];
    const int*   eidx   = (const int*)d_in[2];
    const int*   batch  = (const int*)d_in[3];
    const float* W_emb1 = (const float*)d_in[4];
    const float* b_emb1 = (const float*)d_in[5];
    const float* W_emb2 = (const float*)d_in[6];
    const float* b_emb2 = (const float*)d_in[7];
    const float* Wf     = (const float*)d_in[8];
    const float* bf     = (const float*)d_in[9];
    const float* Ws     = (const float*)d_in[10];
    const float* bs     = (const float*)d_in[11];
    const float* gamma  = (const float*)d_in[12];
    const float* beta   = (const float*)d_in[13];
    const float* W1     = (const float*)d_in[14];
    const float* b1     = (const float*)d_in[15];
    const float* W2     = (const float*)d_in[16];
    const float* b2     = (const float*)d_in[17];
    const float* Wo     = (const float*)d_in[18];
    const float* bo     = (const float*)d_in[19];
    float* out = (float*)d_out;

    const int EDGE_SMEM = (64 * 45 + FE * 128 + 128 + 64 * EFS) * 4 + 128 * 4;
    const int P_SMEM = (64 * 65 + 64 * 256) * 4;
    cudaFuncSetAttribute(k_edge, cudaFuncAttributeMaxDynamicSharedMemorySize, EDGE_SMEM);
    cudaFuncSetAttribute(k_P, cudaFuncAttributeMaxDynamicSharedMemorySize, P_SMEM);

    const int* src = eidx;
    const int* dst = eidx + NE;

    k_init<<<1024, 256>>>(W_emb2, b_emb2, Wf, bf, Ws, bs);
    k_hist<<<1024, 256>>>(dst);
    k_scan1<<<98, 512>>>();
    k_scan2<<<1, 128>>>(98);
    k_scan3<<<(NN + 255) / 256, 256>>>();
    k_scatter<<<1024, 256>>>(dst);
    k_permidx<<<(NE + 255) / 256, 256>>>(src, dst);
    k_emb<<<(NN + 63) / 64, 256>>>(x, W_emb1, b_emb1);

    for (int a = 0; a < NCONV; a++) {
        k_P<<<(NN + 63) / 64, 512, P_SMEM>>>(a, a > 0 ? 1 : 0);
        k_edge<<<NE / 64, 256, EDGE_SMEM>>>(a, ea);
        k_bnstat<<<1024, 256>>>();
        k_bnfin<<<1, 64>>>(gamma + a * H, beta + a * H);
    }
    k_pool<<<1024, 256>>>(batch);
    k_mlp<<<NG, 64>>>(W1, b1, W2, b2, Wo, bo, out);
}

// round 7
// speedup vs baseline: 1.4071x; 1.0191x over previous
#include <cuda_runtime.h>

#define NN 50000
#define NE 800000
#define NG 128
#define FX 92
#define FE 41
#define H  64
#define NCONV 3
#define BN_EPS 1e-5f
#define EFS 130
#define SCANB 98

__device__ float d_h[NN * H];
__device__ float d_agg[NN * H];
__device__ float d_P[NN * 4 * H];
__device__ int   d_perm[NE];
__device__ int   g_srcS[NE];
__device__ int   g_dstS[NE];
__device__ int   d_deg[NN];
__device__ int   d_cursor[NN];
__device__ int   d_ticket;
__device__ volatile int d_bflag[SCANB];
__device__ int   d_bval[SCANB];
__device__ float d_Wcat[NCONV * H * 4 * H];
__device__ float d_Ccomb[NCONV * FE * 2 * H];
__device__ float d_cbias[NCONV * 2 * H];
__device__ float d_colsum[H], d_colsq[H], d_scale[H], d_shift[H];
__device__ float d_gsum[NG * H];
__device__ int   d_gcnt[NG];

__device__ __forceinline__ float sigmoidf_(float x) { return 1.0f / (1.0f + __expf(-x)); }
__device__ __forceinline__ float softplusf_(float x) {
    return fmaxf(x, 0.0f) + __logf(1.0f + __expf(-fabsf(x)));
}
__device__ __forceinline__ unsigned long long packf2(float v) {
    unsigned long long r;
    unsigned int b = __float_as_uint(v);
    asm("mov.b64 %0, {%1, %1};" : "=l"(r) : "r"(b));
    return r;
}
__device__ __forceinline__ void fma2(unsigned long long& acc, unsigned long long a,
                                     unsigned long long b) {
    asm("fma.rn.f32x2 %0, %1, %2, %0;" : "+l"(acc) : "l"(a), "l"(b));
}

// ================= mega0: emb || zero/weight-prep || hist =================
#define EMB_B 782
#define INIT_B 512
#define HIST_B 512

__global__ void __launch_bounds__(256) k_mega0(
        const float* __restrict__ x, const float* __restrict__ Wemb1,
        const float* __restrict__ bemb1,
        const float* __restrict__ W_emb2, const float* __restrict__ b_emb2,
        const float* __restrict__ Wf, const float* __restrict__ bf,
        const float* __restrict__ Ws, const float* __restrict__ bs,
        const int* __restrict__ dst) {
    __shared__ float Xs[64 * 93];
    int bid = blockIdx.x;
    int tid = threadIdx.x;
    if (bid < EMB_B) {
        // ---- node embedding ----
        int base = bid * 64;
        for (int t = tid; t < 64 * FX; t += 256) {
            int r = t / FX, k = t - r * FX;
            int row = base + r;
            Xs[r * 93 + k] = (row < NN) ? x[row * FX + k] : 0.0f;
        }
        __syncthreads();
        int i0 = tid & 31, g = tid >> 5;
        float acc0[8], acc1[8];
#pragma unroll
        for (int m = 0; m < 8; m++) { float bv = bemb1[g * 8 + m]; acc0[m] = bv; acc1[m] = bv; }
        for (int k = 0; k < FX; k++) {
            float a0 = Xs[i0 * 93 + k];
            float a1 = Xs[(i0 + 32) * 93 + k];
            const float4* w = (const float4*)(Wemb1 + k * H + g * 8);
            float4 w0 = w[0], w1 = w[1];
            acc0[0] += a0 * w0.x; acc0[1] += a0 * w0.y; acc0[2] += a0 * w0.z; acc0[3] += a0 * w0.w;
            acc0[4] += a0 * w1.x; acc0[5] += a0 * w1.y; acc0[6] += a0 * w1.z; acc0[7] += a0 * w1.w;
            acc1[0] += a1 * w0.x; acc1[1] += a1 * w0.y; acc1[2] += a1 * w0.z; acc1[3] += a1 * w0.w;
            acc1[4] += a1 * w1.x; acc1[5] += a1 * w1.y; acc1[6] += a1 * w1.z; acc1[7] += a1 * w1.w;
        }
        int r0 = base + i0, r1 = base + i0 + 32;
        if (r0 < NN) {
            float4* o = (float4*)(d_h + r0 * H + g * 8);
            o[0] = make_float4(acc0[0], acc0[1], acc0[2], acc0[3]);
            o[1] = make_float4(acc0[4], acc0[5], acc0[6], acc0[7]);
        }
        if (r1 < NN) {
            float4* o = (float4*)(d_h + r1 * H + g * 8);
            o[0] = make_float4(acc1[0], acc1[1], acc1[2], acc1[3]);
            o[1] = make_float4(acc1[4], acc1[5], acc1[6], acc1[7]);
        }
    } else if (bid < EMB_B + INIT_B) {
        // ---- zero state + fold weights ----
        int stride = INIT_B * 256;
        int tid0 = (bid - EMB_B) * 256 + tid;
        for (int i = tid0; i < NN * H; i += stride) {
            d_agg[i] = 0.0f;
            if (i < NG * H) d_gsum[i] = 0.0f;
            if (i < NG) d_gcnt[i] = 0;
        }
        const int SZ1 = NCONV * H * 4 * H;
        const int SZ2 = NCONV * FE * 2 * H;
        const int SZ3 = NCONV * 2 * H;
        int total = SZ1 + SZ2 + SZ3;
        for (int i = tid0; i < total; i += stride) {
            if (i < SZ1) {
                int a = i / (H * 4 * H);
                int rem = i - a * (H * 4 * H);
                int r = rem / (4 * H);
                int c = rem - r * (4 * H);
                const float* M = ((c >> 6) & 1) ? Ws : Wf;
                int cc = c & 63;
                int rr = (c < 128) ? r : (r + H);
                d_Wcat[i] = M[a * 192 * H + rr * H + cc];
            } else if (i < SZ1 + SZ2) {
                int j = i - SZ1;
                int a = j / (FE * 2 * H);
                int rem = j - a * (FE * 2 * H);
                int k = rem / (2 * H);
                int c = rem - k * (2 * H);
                const float* M = (c < H) ? Wf : Ws;
                int cc = (c < H) ? c : (c - H);
                int base = a * 192 * H + 128 * H;
                float s = 0.0f;
                for (int m = 0; m < H; m++) s += W_emb2[k * H + m] * M[base + m * H + cc];
                d_Ccomb[j] = s;
            } else {
                int j = i - SZ1 - SZ2;
                int a = j / (2 * H);
                int c = j - a * (2 * H);
                const float* M = (c < H) ? Wf : Ws;
                const float* bb = (c < H) ? bf : bs;
                int cc = (c < H) ? c : (c - H);
                int base = a * 192 * H + 128 * H;
                float s = bb[a * H + cc];
                for (int m = 0; m < H; m++) s += b_emb2[m] * M[base + m * H + cc];
                d_cbias[j] = s;
            }
        }
    } else {
        // ---- degree histogram ----
        int stride = HIST_B * 256;
        for (int e = (bid - EMB_B - INIT_B) * 256 + tid; e < NE; e += stride)
            atomicAdd(&d_deg[dst[e]], 1);
    }
}

// ================= P body (shared by mega1 and standalone k_P) =================
__device__ __forceinline__ void P_body(int a, int applyBN, int pb, float* sm, int tid) {
    float* Hs = sm;            // 64*65
    float* Ws = sm + 64 * 65;  // 64*256
    if (pb == 0 && tid < 64) { d_colsum[tid] = 0.0f; d_colsq[tid] = 0.0f; }
    int base = pb * 64;
    for (int t = tid; t < 64 * 64; t += 512) {
        int r = t >> 6, k = t & 63;
        int row = base + r;
        float v = 0.0f;
        if (row < NN) {
            v = d_h[row * H + k];
            if (applyBN) {
                v = fmaxf(fmaf(d_scale[k], v, d_shift[k]), 0.0f);
                d_h[row * H + k] = v;
            }
        }
        Hs[r * 65 + k] = v;
    }
    for (int t = tid; t < 64 * 256; t += 512) Ws[t] = d_Wcat[a * 16384 + t];
    __syncthreads();
    int i = tid & 63, g = tid >> 6;
    unsigned long long acc[16];
#pragma unroll
    for (int m = 0; m < 16; m++) acc[m] = 0ull;
    for (int k = 0; k < 64; k++) {
        unsigned long long av = packf2(Hs[i * 65 + k]);
        const ulonglong2* w = (const ulonglong2*)(Ws + k * 256 + g * 32);
#pragma unroll
        for (int q = 0; q < 8; q++) {
            ulonglong2 wv = w[q];
            fma2(acc[q * 2 + 0], av, wv.x);
            fma2(acc[q * 2 + 1], av, wv.y);
        }
    }
    int row = base + i;
    if (row < NN) {
        unsigned long long* o = (unsigned long long*)(d_P + row * 256 + g * 32);
#pragma unroll
        for (int m = 0; m < 16; m++) o[m] = acc[m];
    }
}

// ================= mega1: chained-lookback scan (98 blocks) || k_P(0) =================
__global__ void __launch_bounds__(512) k_mega1() {
    extern __shared__ float smf[];
    int tid = threadIdx.x;
    if (blockIdx.x < SCANB) {
        __shared__ int s[512];
        __shared__ int sh_rank, sh_pfx;
        if (tid == 0) sh_rank = atomicAdd(&d_ticket, 1);
        __syncthreads();
        int r = sh_rank;
        int i = r * 512 + tid;
        int v = (i < NN) ? d_deg[i] : 0;
        if (i < NN) d_deg[i] = 0;  // self-clean for next call
        s[tid] = v;
        __syncthreads();
        for (int d = 1; d < 512; d <<= 1) {
            int tv = (tid >= d) ? s[tid - d] : 0;
            __syncthreads();
            s[tid] += tv;
            __syncthreads();
        }
        if (tid == 0) {
            int total = s[511];
            int pfx = 0;
            if (r > 0) {
                while (d_bflag[r - 1] == 0) { }
                __threadfence();
                pfx = d_bval[r - 1];
                d_bflag[r - 1] = 0;  // self-clean
            }
            if (r < SCANB - 1) {
                d_bval[r] = pfx + total;
                __threadfence();
                d_bflag[r] = 1;
            } else {
                d_ticket = 0;        // self-clean
            }
            sh_pfx = pfx;
        }
        __syncthreads();
        if (i < NN) d_cursor[i] = sh_pfx + s[tid] - v;  // exclusive global prefix
    } else {
        P_body(0, 0, blockIdx.x - SCANB, smf, tid);
    }
}

// ================= standalone k_P (layers 1,2; fused BN apply) =================
__global__ void __launch_bounds__(512) k_P(int a) {
    extern __shared__ float smf[];
    P_body(a, 1, blockIdx.x, smf, threadIdx.x);
}

// ================= scatter (+ direct sorted src/dst write) =================
__global__ void k_scatter2(const int* __restrict__ src, const int* __restrict__ dst) {
    int stride = gridDim.x * blockDim.x;
    for (int e = blockIdx.x * blockDim.x + threadIdx.x; e < NE; e += stride) {
        int d = dst[e];
        int p = atomicAdd(&d_cursor[d], 1);
        d_perm[p] = e;
        g_dstS[p] = d;
        g_srcS[p] = src[e];
    }
}

// ================= edge kernel =================
__global__ void __launch_bounds__(256) k_edge(int a, const float* __restrict__ ea) {
    extern __shared__ float sm[];
    float* As    = sm;                 // 64*45
    float* Wcs   = As + 64 * 45;       // 41*128
    float* bias  = Wcs + FE * 128;     // 128
    float* EF    = bias + 128;         // 64*EFS
    int*   dsts  = (int*)(EF + 64 * EFS);
    int*   srcs  = dsts + 64;
    int*   permS = srcs + 64;

    int tid = threadIdx.x;
    int base = blockIdx.x * 64;

    if (tid < 64) dsts[tid] = g_dstS[base + tid];
    else if (tid < 128) srcs[tid - 64] = g_srcS[base + tid - 64];
    else if (tid < 192) permS[tid - 128] = d_perm[base + tid - 128];
    __syncthreads();

    for (int t = tid; t < 64 * FE; t += 256) {
        int r = t / FE, k = t - r * FE;
        As[r * 45 + k] = __ldg(&ea[permS[r] * FE + k]);
    }
    for (int t = tid; t < FE * 128; t += 256) Wcs[t] = d_Ccomb[a * FE * 128 + t];
    if (tid < 128) bias[tid] = d_cbias[a * 128 + tid];
    __syncthreads();

    // phase 2: edge-feature GEMM (f32x2)
    int i0 = tid & 31, g = tid >> 5;
    unsigned long long acc0[8], acc1[8];
#pragma unroll
    for (int m = 0; m < 8; m++) { acc0[m] = 0ull; acc1[m] = 0ull; }
    for (int k = 0; k < FE; k++) {
        unsigned long long a0 = packf2(As[i0 * 45 + k]);
        unsigned long long a1 = packf2(As[(i0 + 32) * 45 + k]);
        const ulonglong2* w = (const ulonglong2*)(Wcs + k * 128 + g * 16);
#pragma unroll
        for (int q = 0; q < 4; q++) {
            ulonglong2 wv = w[q];
            fma2(acc0[q * 2 + 0], a0, wv.x);
            fma2(acc0[q * 2 + 1], a0, wv.y);
            fma2(acc1[q * 2 + 0], a1, wv.x);
            fma2(acc1[q * 2 + 1], a1, wv.y);
        }
    }
#pragma unroll
    for (int m = 0; m < 8; m++) {
        *(unsigned long long*)(&EF[i0 * EFS + g * 16 + 2 * m]) = acc0[m];
        *(unsigned long long*)(&EF[(i0 + 32) * EFS + g * 16 + 2 * m]) = acc1[m];
    }
    __syncthreads();

    // phase 3: add node parts, gate -> msg in-place
    int c = tid & 63;
    int esub = tid >> 6;
#pragma unroll 4
    for (int it = 0; it < 16; it++) {
        int ei = it * 4 + esub;
        int dn = dsts[ei], sn = srcs[ei];
        float af = EF[ei * EFS + c] + bias[c]
                 + __ldg(&d_P[dn * 256 + c]) + __ldg(&d_P[sn * 256 + 128 + c]);
        float as_ = EF[ei * EFS + 64 + c] + bias[64 + c]
                  + __ldg(&d_P[dn * 256 + 64 + c]) + __ldg(&d_P[sn * 256 + 192 + c]);
        EF[ei * EFS + c] = sigmoidf_(af) * softplusf_(as_);
    }
    __syncthreads();

    // phase 4: sorted segment-sum, 4 chunks x 16 edges
    {
        int q = tid >> 6;
        int e0 = q * 16;
        float run = 0.0f;
        int prev = dsts[e0];
        for (int e = e0; e < e0 + 16; e++) {
            int dn = dsts[e];
            if (dn != prev) {
                atomicAdd(&d_agg[prev * 64 + c], run);
                run = 0.0f;
                prev = dn;
            }
            run += EF[e * EFS + c];
        }
        atomicAdd(&d_agg[prev * 64 + c], run);
    }
}

// ================= BN stats =================
__global__ void k_bnstat() {
    int tid = threadIdx.x;
    int stride = gridDim.x * blockDim.x;
    float s = 0.0f, sq = 0.0f;
    for (int idx = blockIdx.x * blockDim.x + tid; idx < NN * H; idx += stride) {
        float v = d_h[idx] + d_agg[idx];
        d_h[idx] = v;
        d_agg[idx] = 0.0f;
        s += v;
        sq += v * v;
    }
    __shared__ float ss[256], qq[256];
    ss[tid] = s; qq[tid] = sq;
    __syncthreads();
    if (tid < 64) {
        float S = ss[tid] + ss[tid + 64] + ss[tid + 128] + ss[tid + 192];
        float Q = qq[tid] + qq[tid + 64] + qq[tid + 128] + qq[tid + 192];
        atomicAdd(&d_colsum[tid], S);
        atomicAdd(&d_colsq[tid], Q);
    }
}

__global__ void k_bnfin(const float* __restrict__ gamma, const float* __restrict__ beta) {
    int c = threadIdx.x;
    float mu = d_colsum[c] / (float)NN;
    float var = d_colsq[c] / (float)NN - mu * mu;
    var = fmaxf(var, 0.0f);
    float sc = gamma[c] * rsqrtf(var + BN_EPS);
    d_scale[c] = sc;
    d_shift[c] = beta[c] - mu * sc;
}

// ================= last BN apply + pool =================
__global__ void k_pool(const int* __restrict__ batch) {
    int stride = gridDim.x * blockDim.x;
    for (int idx = blockIdx.x * blockDim.x + threadIdx.x; idx < NN * H; idx += stride) {
        int c = idx & 63;
        float v = fmaf(d_scale[c], d_h[idx], d_shift[c]);
        int r = idx >> 6;
        int gi = batch[r];
        atomicAdd(&d_gsum[gi * H + c], v);
        if (c == 0) atomicAdd(&d_gcnt[gi], 1);
    }
}

// ================= MLP head =================
__global__ void k_mlp(const float* __restrict__ W1, const float* __restrict__ b1,
                      const float* __restrict__ W2, const float* __restrict__ b2,
                      const float* __restrict__ Wo, const float* __restrict__ bo,
                      float* __restrict__ out) {
    __shared__ float gv[64], y[64], red[64];
    int gi = blockIdx.x, c = threadIdx.x;
    float cnt = fmaxf((float)d_gcnt[gi], 1.0f);
    gv[c] = d_gsum[gi * H + c] / cnt;
    __syncthreads();
    float acc = b1[c];
    for (int k = 0; k < 64; k++) acc += gv[k] * W1[k * 64 + c];
    y[c] = softplusf_(acc);
    __syncthreads();
    acc = b2[c];
    for (int k = 0; k < 64; k++) acc += y[k] * W2[k * 64 + c];
    float y2 = softplusf_(acc);
    red[c] = y2 * Wo[c];
    __syncthreads();
    for (int s = 32; s > 0; s >>= 1) {
        if (c < s) red[c] += red[c + s];
        __syncthreads();
    }
    if (c == 0) out[gi] = red[0] + bo[0];
}

extern "C" void kernel_launch(void* const* d_in, const int* in_sizes, int n_in,
                              void* d_out, int out_size) {
    const float* x      = (const float*)d_in[0];
    const float* ea     = (const float*)d_in[1];
    const int*   eidx   = (const int*)d_in[2];
    const int*   batch  = (const int*)d_in[3];
    const float* W_emb1 = (const float*)d_in[4];
    const float* b_emb1 = (const float*)d_in[5];
    const float* W_emb2 = (const float*)d_in[6];
    const float* b_emb2 = (const float*)d_in[7];
    const float* Wf     = (const float*)d_in[8];
    const float* bf     = (const float*)d_in[9];
    const float* Ws     = (const float*)d_in[10];
    const float* bs     = (const float*)d_in[11];
    const float* gamma  = (const float*)d_in[12];
    const float* beta   = (const float*)d_in[13];
    const float* W1     = (const float*)d_in[14];
    const float* b1     = (const float*)d_in[15];
    const float* W2     = (const float*)d_in[16];
    const float* b2     = (const float*)d_in[17];
    const float* Wo     = (const float*)d_in[18];
    const float* bo     = (const float*)d_in[19];
    float* out = (float*)d_out;

    const int EDGE_SMEM = (64 * 45 + FE * 128 + 128 + 64 * EFS) * 4 + 192 * 4;
    const int P_SMEM = (64 * 65 + 64 * 256) * 4;
    cudaFuncSetAttribute(k_edge, cudaFuncAttributeMaxDynamicSharedMemorySize, EDGE_SMEM);
    cudaFuncSetAttribute(k_P, cudaFuncAttributeMaxDynamicSharedMemorySize, P_SMEM);
    cudaFuncSetAttribute(k_mega1, cudaFuncAttributeMaxDynamicSharedMemorySize, P_SMEM);

    const int* src = eidx;
    const int* dst = eidx + NE;

    // launch 0: emb || zero+weight-fold || hist
    k_mega0<<<EMB_B + INIT_B + HIST_B, 256>>>(x, W_emb1, b_emb1,
                                              W_emb2, b_emb2, Wf, bf, Ws, bs, dst);
    // launch 1: chained scan || k_P(0)
    k_mega1<<<SCANB + (NN + 63) / 64, 512, P_SMEM>>>();
    // launch 2: scatter + sorted index write
    k_scatter2<<<1024, 256>>>(src, dst);
    // launch 3: k_edge layer 0  <-- profiled launch index
    k_edge<<<NE / 64, 256, EDGE_SMEM>>>(0, ea);
    k_bnstat<<<1024, 256>>>();
    k_bnfin<<<1, 64>>>(gamma, beta);

    for (int a = 1; a < NCONV; a++) {
        k_P<<<(NN + 63) / 64, 512, P_SMEM>>>(a);
        k_edge<<<NE / 64, 256, EDGE_SMEM>>>(a, ea);
        k_bnstat<<<1024, 256>>>();
        k_bnfin<<<1, 64>>>(gamma + a * H, beta + a * H);
    }
    k_pool<<<1024, 256>>>(batch);
    k_mlp<<<NG, 64>>>(W1, b1, W2, b2, Wo, bo, out);
}

// round 10
// speedup vs baseline: 1.6805x; 1.1943x over previous
#include <cuda_runtime.h>

#define NN 50000
#define NE 800000
#define NG 128
#define FX 92
#define FE 41
#define H  64
#define NCONV 3
#define BN_EPS 1e-5f
#define MSS 66
#define SCANB 98

__device__ float d_h[NN * H];
__device__ float d_agg[NN * H];
__device__ float d_P[NN * 4 * H];
__device__ int   d_perm[NE];
__device__ int   g_srcS[NE];
__device__ int   g_dstS[NE];
__device__ int   d_deg[NN];
__device__ int   d_cursor[NN];
__device__ int   d_ticket;
__device__ volatile int d_bflag[SCANB];
__device__ int   d_bval[SCANB];
__device__ float d_Wcat[NCONV * H * 4 * H];
__device__ float d_Ccomb[NCONV * FE * 2 * H];
__device__ float d_cbias[NCONV * 2 * H];
__device__ float d_colsum[H], d_colsq[H], d_scale[H], d_shift[H];
__device__ float d_gsum[NG * H];
__device__ int   d_gcnt[NG];

__device__ __forceinline__ float sigmoidf_(float x) { return 1.0f / (1.0f + __expf(-x)); }
__device__ __forceinline__ float softplusf_(float x) {
    return fmaxf(x, 0.0f) + __logf(1.0f + __expf(-fabsf(x)));
}
__device__ __forceinline__ unsigned long long packf2(float v) {
    unsigned long long r;
    unsigned int b = __float_as_uint(v);
    asm("mov.b64 %0, {%1, %1};" : "=l"(r) : "r"(b));
    return r;
}
__device__ __forceinline__ void fma2(unsigned long long& acc, unsigned long long a,
                                     unsigned long long b) {
    asm("fma.rn.f32x2 %0, %1, %2, %0;" : "+l"(acc) : "l"(a), "l"(b));
}
__device__ __forceinline__ float lo32(unsigned long long v) {
    unsigned int a, b;
    asm("mov.b64 {%0, %1}, %2;" : "=r"(a), "=r"(b) : "l"(v));
    return __uint_as_float(a);
}
__device__ __forceinline__ float hi32(unsigned long long v) {
    unsigned int a, b;
    asm("mov.b64 {%0, %1}, %2;" : "=r"(a), "=r"(b) : "l"(v));
    return __uint_as_float(b);
}

// ================= mega0: emb || zero/weight-prep || hist =================
#define EMB_B 782
#define INIT_B 512
#define HIST_B 512

__global__ void __launch_bounds__(256) k_mega0(
        const float* __restrict__ x, const float* __restrict__ Wemb1,
        const float* __restrict__ bemb1,
        const float* __restrict__ W_emb2, const float* __restrict__ b_emb2,
        const float* __restrict__ Wf, const float* __restrict__ bf,
        const float* __restrict__ Ws, const float* __restrict__ bs,
        const int* __restrict__ dst) {
    __shared__ float Xs[64 * 93];
    int bid = blockIdx.x;
    int tid = threadIdx.x;
    if (bid < EMB_B) {
        int base = bid * 64;
        for (int t = tid; t < 64 * FX; t += 256) {
            int r = t / FX, k = t - r * FX;
            int row = base + r;
            Xs[r * 93 + k] = (row < NN) ? x[row * FX + k] : 0.0f;
        }
        __syncthreads();
        int i0 = tid & 31, g = tid >> 5;
        float acc0[8], acc1[8];
#pragma unroll
        for (int m = 0; m < 8; m++) { float bv = bemb1[g * 8 + m]; acc0[m] = bv; acc1[m] = bv; }
        for (int k = 0; k < FX; k++) {
            float a0 = Xs[i0 * 93 + k];
            float a1 = Xs[(i0 + 32) * 93 + k];
            const float4* w = (const float4*)(Wemb1 + k * H + g * 8);
            float4 w0 = w[0], w1 = w[1];
            acc0[0] += a0 * w0.x; acc0[1] += a0 * w0.y; acc0[2] += a0 * w0.z; acc0[3] += a0 * w0.w;
            acc0[4] += a0 * w1.x; acc0[5] += a0 * w1.y; acc0[6] += a0 * w1.z; acc0[7] += a0 * w1.w;
            acc1[0] += a1 * w0.x; acc1[1] += a1 * w0.y; acc1[2] += a1 * w0.z; acc1[3] += a1 * w0.w;
            acc1[4] += a1 * w1.x; acc1[5] += a1 * w1.y; acc1[6] += a1 * w1.z; acc1[7] += a1 * w1.w;
        }
        int r0 = base + i0, r1 = base + i0 + 32;
        if (r0 < NN) {
            float4* o = (float4*)(d_h + r0 * H + g * 8);
            o[0] = make_float4(acc0[0], acc0[1], acc0[2], acc0[3]);
            o[1] = make_float4(acc0[4], acc0[5], acc0[6], acc0[7]);
        }
        if (r1 < NN) {
            float4* o = (float4*)(d_h + r1 * H + g * 8);
            o[0] = make_float4(acc1[0], acc1[1], acc1[2], acc1[3]);
            o[1] = make_float4(acc1[4], acc1[5], acc1[6], acc1[7]);
        }
    } else if (bid < EMB_B + INIT_B) {
        int stride = INIT_B * 256;
        int tid0 = (bid - EMB_B) * 256 + tid;
        for (int i = tid0; i < NN * H; i += stride) {
            d_agg[i] = 0.0f;
            if (i < NG * H) d_gsum[i] = 0.0f;
            if (i < NG) d_gcnt[i] = 0;
        }
        const int SZ1 = NCONV * H * 4 * H;
        const int SZ2 = NCONV * FE * 2 * H;
        const int SZ3 = NCONV * 2 * H;
        int total = SZ1 + SZ2 + SZ3;
        for (int i = tid0; i < total; i += stride) {
            if (i < SZ1) {
                int a = i / (H * 4 * H);
                int rem = i - a * (H * 4 * H);
                int r = rem / (4 * H);
                int c = rem - r * (4 * H);
                const float* M = ((c >> 6) & 1) ? Ws : Wf;
                int cc = c & 63;
                int rr = (c < 128) ? r : (r + H);
                d_Wcat[i] = M[a * 192 * H + rr * H + cc];
            } else if (i < SZ1 + SZ2) {
                int j = i - SZ1;
                int a = j / (FE * 2 * H);
                int rem = j - a * (FE * 2 * H);
                int k = rem / (2 * H);
                int c = rem - k * (2 * H);
                const float* M = (c < H) ? Wf : Ws;
                int cc = (c < H) ? c : (c - H);
                int base = a * 192 * H + 128 * H;
                float s = 0.0f;
                for (int m = 0; m < H; m++) s += W_emb2[k * H + m] * M[base + m * H + cc];
                d_Ccomb[j] = s;
            } else {
                int j = i - SZ1 - SZ2;
                int a = j / (2 * H);
                int c = j - a * (2 * H);
                const float* M = (c < H) ? Wf : Ws;
                const float* bb = (c < H) ? bf : bs;
                int cc = (c < H) ? c : (c - H);
                int base = a * 192 * H + 128 * H;
                float s = bb[a * H + cc];
                for (int m = 0; m < H; m++) s += b_emb2[m] * M[base + m * H + cc];
                d_cbias[j] = s;
            }
        }
    } else {
        int stride = HIST_B * 256;
        for (int e = (bid - EMB_B - INIT_B) * 256 + tid; e < NE; e += stride)
            atomicAdd(&d_deg[dst[e]], 1);
    }
}

// ================= P body =================
__device__ __forceinline__ void P_body(int a, int applyBN, int pb, float* sm, int tid) {
    float* Hs = sm;
    float* Ws = sm + 64 * 65;
    if (pb == 0 && tid < 64) { d_colsum[tid] = 0.0f; d_colsq[tid] = 0.0f; }
    int base = pb * 64;
    for (int t = tid; t < 64 * 64; t += 512) {
        int r = t >> 6, k = t & 63;
        int row = base + r;
        float v = 0.0f;
        if (row < NN) {
            v = d_h[row * H + k];
            if (applyBN) {
                v = fmaxf(fmaf(d_scale[k], v, d_shift[k]), 0.0f);
                d_h[row * H + k] = v;
            }
        }
        Hs[r * 65 + k] = v;
    }
    for (int t = tid; t < 64 * 256; t += 512) Ws[t] = d_Wcat[a * 16384 + t];
    __syncthreads();
    int i = tid & 63, g = tid >> 6;
    unsigned long long acc[16];
#pragma unroll
    for (int m = 0; m < 16; m++) acc[m] = 0ull;
    for (int k = 0; k < 64; k++) {
        unsigned long long av = packf2(Hs[i * 65 + k]);
        const ulonglong2* w = (const ulonglong2*)(Ws + k * 256 + g * 32);
#pragma unroll
        for (int q = 0; q < 8; q++) {
            ulonglong2 wv = w[q];
            fma2(acc[q * 2 + 0], av, wv.x);
            fma2(acc[q * 2 + 1], av, wv.y);
        }
    }
    int row = base + i;
    if (row < NN) {
        unsigned long long* o = (unsigned long long*)(d_P + row * 256 + g * 32);
#pragma unroll
        for (int m = 0; m < 16; m++) o[m] = acc[m];
    }
}

// ================= mega1: chained scan || k_P(0) =================
__global__ void __launch_bounds__(512) k_mega1() {
    extern __shared__ float smf[];
    int tid = threadIdx.x;
    if (blockIdx.x < SCANB) {
        __shared__ int s[512];
        __shared__ int sh_rank, sh_pfx;
        if (tid == 0) sh_rank = atomicAdd(&d_ticket, 1);
        __syncthreads();
        int r = sh_rank;
        int i = r * 512 + tid;
        int v = (i < NN) ? d_deg[i] : 0;
        if (i < NN) d_deg[i] = 0;
        s[tid] = v;
        __syncthreads();
        for (int d = 1; d < 512; d <<= 1) {
            int tv = (tid >= d) ? s[tid - d] : 0;
            __syncthreads();
            s[tid] += tv;
            __syncthreads();
        }
        if (tid == 0) {
            int total = s[511];
            int pfx = 0;
            if (r > 0) {
                while (d_bflag[r - 1] == 0) { }
                __threadfence();
                pfx = d_bval[r - 1];
                d_bflag[r - 1] = 0;
            }
            if (r < SCANB - 1) {
                d_bval[r] = pfx + total;
                __threadfence();
                d_bflag[r] = 1;
            } else {
                d_ticket = 0;
            }
            sh_pfx = pfx;
        }
        __syncthreads();
        if (i < NN) d_cursor[i] = sh_pfx + s[tid] - v;
    } else {
        P_body(0, 0, blockIdx.x - SCANB, smf, tid);
    }
}

__global__ void __launch_bounds__(512) k_P(int a) {
    extern __shared__ float smf[];
    P_body(a, 1, blockIdx.x, smf, threadIdx.x);
}

// ================= scatter =================
__global__ void k_scatter2(const int* __restrict__ src, const int* __restrict__ dst) {
    int stride = gridDim.x * blockDim.x;
    for (int e = blockIdx.x * blockDim.x + threadIdx.x; e < NE; e += stride) {
        int d = dst[e];
        int p = atomicAdd(&d_cursor[d], 1);
        d_perm[p] = e;
        g_dstS[p] = d;
        g_srcS[p] = src[e];
    }
}

// ================= edge kernel (register-resident gate, vector gathers) =================
__global__ void __launch_bounds__(256, 4) k_edge(int a, const float* __restrict__ ea) {
    extern __shared__ float sm[];
    float* As    = sm;                  // 64*45
    float* Wcs   = As + 64 * 45;        // 41*128
    float* bias  = Wcs + FE * 128;      // 128
    float* MS    = bias + 128;          // 64*MSS
    int*   dsts  = (int*)(MS + 64 * MSS);
    int*   srcs  = dsts + 64;
    int*   permS = srcs + 64;

    int tid = threadIdx.x;
    int base = blockIdx.x * 64;

    if (tid < 64) dsts[tid] = g_dstS[base + tid];
    else if (tid < 128) srcs[tid - 64] = g_srcS[base + tid - 64];
    else if (tid < 192) permS[tid - 128] = d_perm[base + tid - 128];
    __syncthreads();

    for (int t = tid; t < 64 * FE; t += 256) {
        int r = t / FE, k = t - r * FE;
        As[r * 45 + k] = __ldg(&ea[permS[r] * FE + k]);
    }
    for (int t = tid; t < FE * 128; t += 256) Wcs[t] = d_Ccomb[a * FE * 128 + t];
    __syncthreads();

    // phase 2: GEMM. thread (lane, w): edges lane, lane+32; F cols [w*8,w*8+8), S cols 64+[w*8..)
    int lane = tid & 31, w = tid >> 5;
    int cb = w * 8;
    unsigned long long aF0[4], aS0[4], aF1[4], aS1[4];
#pragma unroll
    for (int m = 0; m < 4; m++) { aF0[m] = 0ull; aS0[m] = 0ull; aF1[m] = 0ull; aS1[m] = 0ull; }
    for (int k = 0; k < FE; k++) {
        unsigned long long a0 = packf2(As[lane * 45 + k]);
        unsigned long long a1 = packf2(As[(lane + 32) * 45 + k]);
        const ulonglong2* wF = (const ulonglong2*)(Wcs + k * 128 + cb);
        const ulonglong2* wS = (const ulonglong2*)(Wcs + k * 128 + 64 + cb);
        ulonglong2 f0 = wF[0], f1 = wF[1];
        ulonglong2 s0 = wS[0], s1 = wS[1];
        fma2(aF0[0], a0, f0.x); fma2(aF0[1], a0, f0.y);
        fma2(aF0[2], a0, f1.x); fma2(aF0[3], a0, f1.y);
        fma2(aS0[0], a0, s0.x); fma2(aS0[1], a0, s0.y);
        fma2(aS0[2], a0, s1.x); fma2(aS0[3], a0, s1.y);
        fma2(aF1[0], a1, f0.x); fma2(aF1[1], a1, f0.y);
        fma2(aF1[2], a1, f1.x); fma2(aF1[3], a1, f1.y);
        fma2(aS1[0], a1, s0.x); fma2(aS1[1], a1, s0.y);
        fma2(aS1[2], a1, s1.x); fma2(aS1[3], a1, s1.y);
    }

    // biases (broadcast within warp)
    const float* cb_ = d_cbias + a * 128;
    float bF[8], bS[8];
#pragma unroll
    for (int j = 0; j < 8; j++) { bF[j] = __ldg(&cb_[cb + j]); bS[j] = __ldg(&cb_[64 + cb + j]); }

    // phase 3: gate in registers, vector P gathers, write msg to MS
#pragma unroll
    for (int e2 = 0; e2 < 2; e2++) {
        int ei = lane + e2 * 32;
        int dn = dsts[ei], sn = srcs[ei];
        const float4* pdF = (const float4*)(d_P + dn * 256 + cb);
        const float4* psF = (const float4*)(d_P + sn * 256 + 128 + cb);
        const float4* pdS = (const float4*)(d_P + dn * 256 + 64 + cb);
        const float4* psS = (const float4*)(d_P + sn * 256 + 192 + cb);
        float4 dF0 = pdF[0], dF1 = pdF[1];
        float4 sF0 = psF[0], sF1 = psF[1];
        float4 dS0 = pdS[0], dS1 = pdS[1];
        float4 sS0 = psS[0], sS1 = psS[1];
        const unsigned long long* AF = e2 ? aF1 : aF0;
        const unsigned long long* AS = e2 ? aS1 : aS0;
        float fv[8], sv[8];
        fv[0] = lo32(AF[0]) + bF[0] + dF0.x + sF0.x;
        fv[1] = hi32(AF[0]) + bF[1] + dF0.y + sF0.y;
        fv[2] = lo32(AF[1]) + bF[2] + dF0.z + sF0.z;
        fv[3] = hi32(AF[1]) + bF[3] + dF0.w + sF0.w;
        fv[4] = lo32(AF[2]) + bF[4] + dF1.x + sF1.x;
        fv[5] = hi32(AF[2]) + bF[5] + dF1.y + sF1.y;
        fv[6] = lo32(AF[3]) + bF[6] + dF1.z + sF1.z;
        fv[7] = hi32(AF[3]) + bF[7] + dF1.w + sF1.w;
        sv[0] = lo32(AS[0]) + bS[0] + dS0.x + sS0.x;
        sv[1] = hi32(AS[0]) + bS[1] + dS0.y + sS0.y;
        sv[2] = lo32(AS[1]) + bS[2] + dS0.z + sS0.z;
        sv[3] = hi32(AS[1]) + bS[3] + dS0.w + sS0.w;
        sv[4] = lo32(AS[2]) + bS[4] + dS1.x + sS1.x;
        sv[5] = hi32(AS[2]) + bS[5] + dS1.y + sS1.y;
        sv[6] = lo32(AS[3]) + bS[6] + dS1.z + sS1.z;
        sv[7] = hi32(AS[3]) + bS[7] + dS1.w + sS1.w;
        float* msp = MS + ei * MSS + cb;
#pragma unroll
        for (int j = 0; j < 8; j += 2) {
            float m0 = sigmoidf_(fv[j]) * softplusf_(sv[j]);
            float m1 = sigmoidf_(fv[j + 1]) * softplusf_(sv[j + 1]);
            *(float2*)(msp + j) = make_float2(m0, m1);
        }
    }
    __syncthreads();

    // phase 4: sorted segment-sum, 4 chunks x 16 edges
    {
        int c = tid & 63;
        int q = tid >> 6;
        int e0 = q * 16;
        float run = 0.0f;
        int prev = dsts[e0];
        for (int e = e0; e < e0 + 16; e++) {
            int dn = dsts[e];
            if (dn != prev) {
                atomicAdd(&d_agg[prev * 64 + c], run);
                run = 0.0f;
                prev = dn;
            }
            run += MS[e * MSS + c];
        }
        atomicAdd(&d_agg[prev * 64 + c], run);
    }
}

// ================= BN stats =================
__global__ void k_bnstat() {
    int tid = threadIdx.x;
    int stride = gridDim.x * blockDim.x;
    float s = 0.0f, sq = 0.0f;
    for (int idx = blockIdx.x * blockDim.x + tid; idx < NN * H; idx += stride) {
        float v = d_h[idx] + d_agg[idx];
        d_h[idx] = v;
        d_agg[idx] = 0.0f;
        s += v;
        sq += v * v;
    }
    __shared__ float ss[256], qq[256];
    ss[tid] = s; qq[tid] = sq;
    __syncthreads();
    if (tid < 64) {
        float S = ss[tid] + ss[tid + 64] + ss[tid + 128] + ss[tid + 192];
        float Q = qq[tid] + qq[tid + 64] + qq[tid + 128] + qq[tid + 192];
        atomicAdd(&d_colsum[tid], S);
        atomicAdd(&d_colsq[tid], Q);
    }
}

__global__ void k_bnfin(const float* __restrict__ gamma, const float* __restrict__ beta) {
    int c = threadIdx.x;
    float mu = d_colsum[c] / (float)NN;
    float var = d_colsq[c] / (float)NN - mu * mu;
    var = fmaxf(var, 0.0f);
    float sc = gamma[c] * rsqrtf(var + BN_EPS);
    d_scale[c] = sc;
    d_shift[c] = beta[c] - mu * sc;
}

// ================= last BN apply + pool =================
__global__ void k_pool(const int* __restrict__ batch) {
    int stride = gridDim.x * blockDim.x;
    for (int idx = blockIdx.x * blockDim.x + threadIdx.x; idx < NN * H; idx += stride) {
        int c = idx & 63;
        float v = fmaf(d_scale[c], d_h[idx], d_shift[c]);
        int r = idx >> 6;
        int gi = batch[r];
        atomicAdd(&d_gsum[gi * H + c], v);
        if (c == 0) atomicAdd(&d_gcnt[gi], 1);
    }
}

// ================= MLP head =================
__global__ void k_mlp(const float* __restrict__ W1, const float* __restrict__ b1,
                      const float* __restrict__ W2, const float* __restrict__ b2,
                      const float* __restrict__ Wo, const float* __restrict__ bo,
                      float* __restrict__ out) {
    __shared__ float gv[64], y[64], red[64];
    int gi = blockIdx.x, c = threadIdx.x;
    float cnt = fmaxf((float)d_gcnt[gi], 1.0f);
    gv[c] = d_gsum[gi * H + c] / cnt;
    __syncthreads();
    float acc = b1[c];
    for (int k = 0; k < 64; k++) acc += gv[k] * W1[k * 64 + c];
    y[c] = softplusf_(acc);
    __syncthreads();
    acc = b2[c];
    for (int k = 0; k < 64; k++) acc += y[k] * W2[k * 64 + c];
    float y2 = softplusf_(acc);
    red[c] = y2 * Wo[c];
    __syncthreads();
    for (int s = 32; s > 0; s >>= 1) {
        if (c < s) red[c] += red[c + s];
        __syncthreads();
    }
    if (c == 0) out[gi] = red[0] + bo[0];
}

extern "C" void kernel_launch(void* const* d_in, const int* in_sizes, int n_in,
                              void* d_out, int out_size) {
    const float* x      = (const float*)d_in[0];
    const float* ea     = (const float*)d_in[1];
    const int*   eidx   = (const int*)d_in[2];
    const int*   batch  = (const int*)d_in[3];
    const float* W_emb1 = (const float*)d_in[4];
    const float* b_emb1 = (const float*)d_in[5];
    const float* W_emb2 = (const float*)d_in[6];
    const float* b_emb2 = (const float*)d_in[7];
    const float* Wf     = (const float*)d_in[8];
    const float* bf     = (const float*)d_in[9];
    const float* Ws     = (const float*)d_in[10];
    const float* bs     = (const float*)d_in[11];
    const float* gamma  = (const float*)d_in[12];
    const float* beta   = (const float*)d_in[13];
    const float* W1     = (const float*)d_in[14];
    const float* b1     = (const float*)d_in[15];
    const float* W2     = (const float*)d_in[16];
    const float* b2     = (const float*)d_in[17];
    const float* Wo     = (const float*)d_in[18];
    const float* bo     = (const float*)d_in[19];
    float* out = (float*)d_out;

    const int EDGE_SMEM = (64 * 45 + FE * 128 + 128 + 64 * MSS) * 4 + 192 * 4;
    const int P_SMEM = (64 * 65 + 64 * 256) * 4;
    cudaFuncSetAttribute(k_edge, cudaFuncAttributeMaxDynamicSharedMemorySize, EDGE_SMEM);
    cudaFuncSetAttribute(k_P, cudaFuncAttributeMaxDynamicSharedMemorySize, P_SMEM);
    cudaFuncSetAttribute(k_mega1, cudaFuncAttributeMaxDynamicSharedMemorySize, P_SMEM);

    const int* src = eidx;
    const int* dst = eidx + NE;

    k_mega0<<<EMB_B + INIT_B + HIST_B, 256>>>(x, W_emb1, b_emb1,
                                              W_emb2, b_emb2, Wf, bf, Ws, bs, dst);
    k_mega1<<<SCANB + (NN + 63) / 64, 512, P_SMEM>>>();
    k_scatter2<<<1024, 256>>>(src, dst);
    k_edge<<<NE / 64, 256, EDGE_SMEM>>>(0, ea);   // launch 3 (profiled)
    k_bnstat<<<1024, 256>>>();
    k_bnfin<<<1, 64>>>(gamma, beta);

    for (int a = 1; a < NCONV; a++) {
        k_P<<<(NN + 63) / 64, 512, P_SMEM>>>(a);
        k_edge<<<NE / 64, 256, EDGE_SMEM>>>(a, ea);
        k_bnstat<<<1024, 256>>>();
        k_bnfin<<<1, 64>>>(gamma + a * H, beta + a * H);
    }
    k_pool<<<1024, 256>>>(batch);
    k_mlp<<<NG, 64>>>(W1, b1, W2, b2, Wo, bo, out);
}